// round 1
// baseline (speedup 1.0000x reference)
#include <cuda_runtime.h>

// Problem constants
#define NB 2
#define LB 1024
#define EB 256
#define HB 8
#define PB 4
#define KK 4
#define DB 32
#define MROWS (NB*LB)        // 2048
#define NH (NB*HB)           // 16
#define QPB (LB*PB)          // 4096 queries per batch
#define QTOT (NH*QPB)        // 65536

// ---------------- scratch (device globals; no allocation allowed) ----------
__device__ float  g_val [MROWS*EB];          // value = q@W_val+b  (N,L,E) row-major
__device__ float  g_off [MROWS*HB*PB*3];     // q@W_off+b          (m,96)
__device__ float  g_attn[MROWS*HB*PB];       // q@W_attn+b         (m,32)
__device__ float  g_attw[QTOT];              // softmax weights, indexed by q = b*4096+l*4+p
__device__ float4 g_sl  [QTOT];              // sampling loc (x,y,z,|s|^2)
__device__ int    g_idx [QTOT*KK];           // top-4 neighbor indices
__device__ float  g_w   [QTOT*KK];           // combined weight attw * idw_norm
__device__ float  g_A   [MROWS*EB];          // pre-output (N,L,E) before W_out

// ---------------- generic 64x64 tiled SGEMM with bias ----------------------
// C[M=2048, NC] = A[2048,256] @ B[256,NC] + bias ; block = 256 threads, 4x4/thread
template<int NC>
__device__ __forceinline__ void sgemm_body(const float* __restrict__ A,
                                           const float* __restrict__ B,
                                           const float* __restrict__ bias,
                                           float* __restrict__ C) {
    const int K = 256;
    __shared__ float As[16][64];
    __shared__ float Bs[16][68];   // pad to dodge conflicts
    const int tid = threadIdx.x;
    const int tx = tid & 15, ty = tid >> 4;
    const int rowBase = blockIdx.y * 64;
    const int colBase = blockIdx.x * 64;
    float acc[4][4];
    #pragma unroll
    for (int i = 0; i < 4; i++)
        #pragma unroll
        for (int j = 0; j < 4; j++) acc[i][j] = 0.f;

    for (int k0 = 0; k0 < K; k0 += 16) {
        #pragma unroll
        for (int i = 0; i < 4; i++) {
            int idx = tid + i*256;           // 0..1023
            int m = idx >> 4, k = idx & 15;
            As[k][m] = A[(rowBase + m)*K + k0 + k];
        }
        #pragma unroll
        for (int i = 0; i < 4; i++) {
            int idx = tid + i*256;
            int k = idx >> 6, n = idx & 63;
            int gn = colBase + n;
            float v = 0.f;
            if ((NC & 63) == 0 || gn < NC) v = B[(k0 + k)*NC + gn];
            Bs[k][n] = v;
        }
        __syncthreads();
        #pragma unroll
        for (int kk = 0; kk < 16; kk++) {
            float a[4], b[4];
            #pragma unroll
            for (int i = 0; i < 4; i++) a[i] = As[kk][ty*4 + i];
            #pragma unroll
            for (int j = 0; j < 4; j++) b[j] = Bs[kk][tx*4 + j];
            #pragma unroll
            for (int i = 0; i < 4; i++)
                #pragma unroll
                for (int j = 0; j < 4; j++)
                    acc[i][j] = fmaf(a[i], b[j], acc[i][j]);
        }
        __syncthreads();
    }
    #pragma unroll
    for (int i = 0; i < 4; i++) {
        int gm = rowBase + ty*4 + i;
        #pragma unroll
        for (int j = 0; j < 4; j++) {
            int gn = colBase + tx*4 + j;
            if ((NC & 63) == 0 || gn < NC)
                C[gm*NC + gn] = acc[i][j] + bias[gn];
        }
    }
}

__global__ void gemm_val_k (const float* A, const float* B, const float* bias){ sgemm_body<256>(A,B,bias,g_val);  }
__global__ void gemm_off_k (const float* A, const float* B, const float* bias){ sgemm_body< 96>(A,B,bias,g_off);  }
__global__ void gemm_attn_k(const float* A, const float* B, const float* bias){ sgemm_body< 32>(A,B,bias,g_attn); }
__global__ void gemm_out_k (const float* B, const float* bias, float* C)      { sgemm_body<256>(g_A,B,bias,C);    }

// ---------------- epilogue: sampling locations + softmax(attn) -------------
// one thread per (n,l,h)
__global__ void epilogue_k(const float* __restrict__ rp) {
    int t = blockIdx.x * blockDim.x + threadIdx.x;
    if (t >= NB*LB*HB) return;
    int h = t & 7;
    int l = (t >> 3) & (LB - 1);
    int n = t >> 13;
    int m = n*LB + l;
    int b = n*HB + h;

    const float* lg = g_attn + m*32 + h*4;
    float x0 = lg[0], x1 = lg[1], x2 = lg[2], x3 = lg[3];
    float mx = fmaxf(fmaxf(x0, x1), fmaxf(x2, x3));
    float e0 = expf(x0 - mx), e1 = expf(x1 - mx), e2 = expf(x2 - mx), e3 = expf(x3 - mx);
    float inv = 1.f / (e0 + e1 + e2 + e3);
    int qb = b*QPB + l*PB;
    g_attw[qb + 0] = e0*inv; g_attw[qb + 1] = e1*inv;
    g_attw[qb + 2] = e2*inv; g_attw[qb + 3] = e3*inv;

    float rx = rp[m*3 + 0], ry = rp[m*3 + 1], rz = rp[m*3 + 2];
    const float* of = g_off + m*96 + h*12;
    #pragma unroll
    for (int p = 0; p < 4; p++) {
        float sx = rx + of[p*3 + 0];
        float sy = ry + of[p*3 + 1];
        float sz = rz + of[p*3 + 2];
        g_sl[qb + p] = make_float4(sx, sy, sz, sx*sx + sy*sy + sz*sz);
    }
}

// ---------------- brute-force top-4 NN over 1024 refs ----------------------
// grid (16 query-chunks, 16 batches), 256 threads; one thread per query
__global__ void knn_k(const float* __restrict__ rp) {
    __shared__ float4 sref[LB];
    int b = blockIdx.y;                    // 0..15
    // reference set for batch b: rp[b % N]  (replicates jnp.tile quirk)
    const float* rpb = rp + (b & (NB - 1)) * LB * 3;
    for (int i = threadIdx.x; i < LB; i += blockDim.x) {
        float x = rpb[i*3], y = rpb[i*3 + 1], z = rpb[i*3 + 2];
        sref[i] = make_float4(x, y, z, x*x + y*y + z*z);
    }
    __syncthreads();

    int qi = blockIdx.x * blockDim.x + threadIdx.x;   // 0..4095
    int q = b*QPB + qi;
    float4 s = g_sl[q];

    float d0 = 3.4e38f, d1 = 3.4e38f, d2 = 3.4e38f, d3 = 3.4e38f;
    int   i0 = 0, i1 = 0, i2 = 0, i3 = 0;
    #pragma unroll 4
    for (int i = 0; i < LB; i++) {
        float4 r = sref[i];
        float dot = s.x*r.x + s.y*r.y + s.z*r.z;
        float dd = s.w + fmaf(-2.f, dot, r.w);   // same formula as reference
        if (dd < d3) {
            if (dd < d2) {
                d3 = d2; i3 = i2;
                if (dd < d1) {
                    d2 = d1; i2 = i1;
                    if (dd < d0) { d1 = d0; i1 = i0; d0 = dd; i0 = i; }
                    else         { d1 = dd; i1 = i; }
                } else { d2 = dd; i2 = i; }
            } else { d3 = dd; i3 = i; }
        }
    }
    float t0 = sqrtf(fmaxf(d0, 1e-12f));
    float t1 = sqrtf(fmaxf(d1, 1e-12f));
    float t2 = sqrtf(fmaxf(d2, 1e-12f));
    float t3 = sqrtf(fmaxf(d3, 1e-12f));
    float w0 = 1.f/(t0 + 1e-8f), w1 = 1.f/(t1 + 1e-8f);
    float w2 = 1.f/(t2 + 1e-8f), w3 = 1.f/(t3 + 1e-8f);
    float scale = g_attw[q] / (w0 + w1 + w2 + w3);
    g_idx[q*4 + 0] = i0; g_idx[q*4 + 1] = i1; g_idx[q*4 + 2] = i2; g_idx[q*4 + 3] = i3;
    g_w  [q*4 + 0] = w0*scale; g_w[q*4 + 1] = w1*scale;
    g_w  [q*4 + 2] = w2*scale; g_w[q*4 + 3] = w3*scale;
}

// ---------------- gather values + weighted sum over (p, k) -----------------
// one warp per (b,l); lane = d channel
__global__ void combine_k() {
    int gw = (blockIdx.x * blockDim.x + threadIdx.x) >> 5;
    int lane = threadIdx.x & 31;
    if (gw >= NH*LB) return;
    int b = gw >> 10;
    int l = gw & (LB - 1);
    int n_q = b >> 3, h_q = b & 7;       // output placement
    int n_v = b & 1,  h_v = b >> 1;      // value slice (reference's transpose quirk)
    const float* vbase = g_val + n_v*(LB*EB) + h_v*DB + lane;
    int qb = (b*QPB + l*PB) * KK;
    float acc = 0.f;
    #pragma unroll
    for (int j = 0; j < 16; j++) {
        int   idx = g_idx[qb + j];
        float wt  = g_w  [qb + j];
        acc = fmaf(wt, vbase[idx*EB], acc);
    }
    g_A[(n_q*LB + l)*EB + h_q*DB + lane] = acc;
}

// ---------------------------------------------------------------------------
extern "C" void kernel_launch(void* const* d_in, const int* in_sizes, int n_in,
                              void* d_out, int out_size) {
    const float* q      = (const float*)d_in[0];
    const float* rp     = (const float*)d_in[1];
    const float* W_off  = (const float*)d_in[2];
    const float* b_off  = (const float*)d_in[3];
    const float* W_attn = (const float*)d_in[4];
    const float* b_attn = (const float*)d_in[5];
    const float* W_val  = (const float*)d_in[6];
    const float* b_val  = (const float*)d_in[7];
    const float* W_out  = (const float*)d_in[8];
    const float* b_out  = (const float*)d_in[9];
    float* out = (float*)d_out;

    dim3 blk(256);
    gemm_val_k <<<dim3(4, 32), blk>>>(q, W_val,  b_val);
    gemm_off_k <<<dim3(2, 32), blk>>>(q, W_off,  b_off);
    gemm_attn_k<<<dim3(1, 32), blk>>>(q, W_attn, b_attn);
    epilogue_k <<<64, blk>>>(rp);
    knn_k      <<<dim3(16, 16), blk>>>(rp);
    combine_k  <<<2048, blk>>>();
    gemm_out_k <<<dim3(4, 32), blk>>>(W_out, b_out, out);
}

// round 2
// speedup vs baseline: 1.1977x; 1.1977x over previous
#include <cuda_runtime.h>

// Problem constants
#define NB 2
#define LB 1024
#define EB 256
#define HB 8
#define PB 4
#define KK 4
#define DB 32
#define MROWS (NB*LB)        // 2048
#define NH (NB*HB)           // 16
#define QPB (LB*PB)          // 4096 queries per batch
#define QTOT (NH*QPB)        // 65536

// ---------------- scratch (device globals; no allocation allowed) ----------
__device__ float  g_val [MROWS*EB];          // value = q@W_val+b   (N,L,E)
__device__ float  g_off [MROWS*96];          // q@W_off+b           (m,96)
__device__ float  g_attn[MROWS*32];          // q@W_attn+b          (m,32)
__device__ int    g_idx [QTOT*KK];           // top-4 neighbor indices
__device__ float  g_w   [QTOT*KK];           // combined weight attw * idw_norm
__device__ float  g_A   [MROWS*EB];          // pre-output (N,L,E) before W_out

// ---------------- packed f32x2 helpers (Blackwell) --------------------------
typedef unsigned long long u64;
__device__ __forceinline__ u64 pk(float lo, float hi) {
    u64 v; asm("mov.b64 %0, {%1, %2};" : "=l"(v) : "f"(lo), "f"(hi)); return v;
}
__device__ __forceinline__ void upk(u64 v, float& lo, float& hi) {
    asm("mov.b64 {%0, %1}, %2;" : "=f"(lo), "=f"(hi) : "l"(v));
}
__device__ __forceinline__ u64 fma2(u64 a, u64 b, u64 c) {
    u64 d; asm("fma.rn.f32x2 %0, %1, %2, %3;" : "=l"(d) : "l"(a), "l"(b), "l"(c)); return d;
}
__device__ __forceinline__ u64 mul2(u64 a, u64 b) {
    u64 d; asm("mul.rn.f32x2 %0, %1, %2;" : "=l"(d) : "l"(a), "l"(b)); return d;
}
__device__ __forceinline__ u64 add2(u64 a, u64 b) {
    u64 d; asm("add.rn.f32x2 %0, %1, %2;" : "=l"(d) : "l"(a), "l"(b)); return d;
}

// ---------------- generic 64x64 tiled SGEMM with bias ----------------------
// C[M=2048, 256] = A[2048,256] @ B[256,256] + bias ; 256 thr, 4x4/thread
__device__ __forceinline__ void sgemm256_body(const float* __restrict__ A,
                                              const float* __restrict__ B,
                                              const float* __restrict__ bias,
                                              float* __restrict__ C) {
    const int K = 256, NC = 256;
    __shared__ float As[16][64];
    __shared__ float Bs[16][68];
    const int tid = threadIdx.x;
    const int tx = tid & 15, ty = tid >> 4;
    const int rowBase = blockIdx.y * 64;
    const int colBase = blockIdx.x * 64;
    float acc[4][4];
    #pragma unroll
    for (int i = 0; i < 4; i++)
        #pragma unroll
        for (int j = 0; j < 4; j++) acc[i][j] = 0.f;

    for (int k0 = 0; k0 < K; k0 += 16) {
        #pragma unroll
        for (int i = 0; i < 4; i++) {
            int idx = tid + i*256;
            int m = idx >> 4, k = idx & 15;
            As[k][m] = A[(rowBase + m)*K + k0 + k];
        }
        #pragma unroll
        for (int i = 0; i < 4; i++) {
            int idx = tid + i*256;
            int k = idx >> 6, n = idx & 63;
            Bs[k][n] = B[(k0 + k)*NC + colBase + n];
        }
        __syncthreads();
        #pragma unroll
        for (int kk = 0; kk < 16; kk++) {
            float4 av = *(const float4*)&As[kk][ty*4];
            float4 bv = *(const float4*)&Bs[kk][tx*4];
            float a[4] = {av.x, av.y, av.z, av.w};
            float b[4] = {bv.x, bv.y, bv.z, bv.w};
            #pragma unroll
            for (int i = 0; i < 4; i++)
                #pragma unroll
                for (int j = 0; j < 4; j++)
                    acc[i][j] = fmaf(a[i], b[j], acc[i][j]);
        }
        __syncthreads();
    }
    #pragma unroll
    for (int i = 0; i < 4; i++) {
        int gm = rowBase + ty*4 + i;
        #pragma unroll
        for (int j = 0; j < 4; j++) {
            int gn = colBase + tx*4 + j;
            C[gm*NC + gn] = acc[i][j] + bias[gn];
        }
    }
}

__global__ void gemm_val_k(const float* A, const float* B, const float* bias) {
    sgemm256_body(A, B, bias, g_val);
}
__global__ void gemm_out_k(const float* B, const float* bias, float* C) {
    sgemm256_body(g_A, B, bias, C);
}

// Merged off(96) + attn(32) projection: 128 virtual columns
__global__ void gemm_oa_k(const float* __restrict__ A,
                          const float* __restrict__ W_off,  const float* __restrict__ b_off,
                          const float* __restrict__ W_attn, const float* __restrict__ b_attn) {
    const int K = 256;
    __shared__ float As[16][64];
    __shared__ float Bs[16][68];
    const int tid = threadIdx.x;
    const int tx = tid & 15, ty = tid >> 4;
    const int rowBase = blockIdx.y * 64;
    const int colBase = blockIdx.x * 64;   // 0 or 64
    float acc[4][4];
    #pragma unroll
    for (int i = 0; i < 4; i++)
        #pragma unroll
        for (int j = 0; j < 4; j++) acc[i][j] = 0.f;

    for (int k0 = 0; k0 < K; k0 += 16) {
        #pragma unroll
        for (int i = 0; i < 4; i++) {
            int idx = tid + i*256;
            int m = idx >> 4, k = idx & 15;
            As[k][m] = A[(rowBase + m)*K + k0 + k];
        }
        #pragma unroll
        for (int i = 0; i < 4; i++) {
            int idx = tid + i*256;
            int k = idx >> 6, n = idx & 63;
            int gn = colBase + n;
            int gk = k0 + k;
            Bs[k][n] = (gn < 96) ? W_off[gk*96 + gn] : W_attn[gk*32 + (gn - 96)];
        }
        __syncthreads();
        #pragma unroll
        for (int kk = 0; kk < 16; kk++) {
            float4 av = *(const float4*)&As[kk][ty*4];
            float4 bv = *(const float4*)&Bs[kk][tx*4];
            float a[4] = {av.x, av.y, av.z, av.w};
            float b[4] = {bv.x, bv.y, bv.z, bv.w};
            #pragma unroll
            for (int i = 0; i < 4; i++)
                #pragma unroll
                for (int j = 0; j < 4; j++)
                    acc[i][j] = fmaf(a[i], b[j], acc[i][j]);
        }
        __syncthreads();
    }
    #pragma unroll
    for (int i = 0; i < 4; i++) {
        int gm = rowBase + ty*4 + i;
        #pragma unroll
        for (int j = 0; j < 4; j++) {
            int gn = colBase + tx*4 + j;
            if (gn < 96) g_off[gm*96 + gn]         = acc[i][j] + b_off[gn];
            else         g_attn[gm*32 + (gn - 96)] = acc[i][j] + b_attn[gn - 96];
        }
    }
}

// ---------------- fused epilogue + brute-force top-4 NN --------------------
// grid (16 query-chunks, 16 batch-heads), 256 threads; one thread per query.
// Slow-path insertion: branchless select ladder (single branch region).
#define INS(dd, ii) { \
    bool c3 = (dd) < d3, c2 = (dd) < d2, c1 = (dd) < d1, c0 = (dd) < d0; \
    d3 = c3 ? (c2 ? d2 : (dd)) : d3;  i3 = c3 ? (c2 ? i2 : (ii)) : i3; \
    d2 = c2 ? (c1 ? d1 : (dd)) : d2;  i2 = c2 ? (c1 ? i1 : (ii)) : i2; \
    d1 = c1 ? (c0 ? d0 : (dd)) : d1;  i1 = c1 ? (c0 ? i0 : (ii)) : i1; \
    d0 = c0 ? (dd) : d0;              i0 = c0 ? (ii) : i0; }

__global__ void knn_k(const float* __restrict__ rp) {
    // refs stored as pair-SoA: sXY[j]=(x0,x1,y0,y1), sZW[j]=(z0,z1,w0,w1)
    __shared__ float4 sXY[LB/2];
    __shared__ float4 sZW[LB/2];
    const int b = blockIdx.y;                         // 0..15 (= n*8+h)
    const float* rpb = rp + (b & (NB-1)) * LB * 3;    // ref set = rp[b % N]
    for (int i = threadIdx.x; i < LB; i += 256) {
        float x = rpb[3*i], y = rpb[3*i+1], z = rpb[3*i+2];
        int j = i >> 1, s = i & 1;
        float* xy = (float*)&sXY[j];
        float* zw = (float*)&sZW[j];
        xy[s] = x;  xy[2+s] = y;
        zw[s] = z;  zw[2+s] = x*x + y*y + z*z;
    }

    // ----- fused epilogue: softmax(attn) + sampling location -----
    const int qi = blockIdx.x * 256 + threadIdx.x;    // 0..4095
    const int l = qi >> 2, p = qi & 3;
    const int n = b >> 3, h = b & 7;
    const int m = n*LB + l;

    float x = g_attn[m*32 + h*4 + p];
    float mx = x;
    mx = fmaxf(mx, __shfl_xor_sync(0xffffffffu, mx, 1));
    mx = fmaxf(mx, __shfl_xor_sync(0xffffffffu, mx, 2));
    float e = expf(x - mx);
    float se = e;
    se += __shfl_xor_sync(0xffffffffu, se, 1);
    se += __shfl_xor_sync(0xffffffffu, se, 2);
    float attw = e / se;

    float rx = rp[m*3], ry = rp[m*3+1], rz = rp[m*3+2];   // query batch n
    const float* of = g_off + m*96 + h*12 + p*3;
    float sx = rx + of[0], sy = ry + of[1], sz = rz + of[2];
    float sw = sx*sx + sy*sy + sz*sz;

    __syncthreads();

    const u64 sx2 = pk(sx, sx), sy2 = pk(sy, sy), sz2 = pk(sz, sz), sw2 = pk(sw, sw);
    const u64 m2 = pk(-2.f, -2.f);

    float d0 = 3.4e38f, d1 = 3.4e38f, d2 = 3.4e38f, d3 = 3.4e38f;
    int   i0 = 0, i1 = 0, i2 = 0, i3 = 0;

    #pragma unroll 4
    for (int j = 0; j < LB/2; j++) {
        float4 xy = sXY[j];
        float4 zw = sZW[j];
        u64 dot = mul2(pk(xy.x, xy.y), sx2);
        dot = fma2(pk(xy.z, xy.w), sy2, dot);
        dot = fma2(pk(zw.x, zw.y), sz2, dot);
        u64 dd2 = fma2(dot, m2, add2(pk(zw.z, zw.w), sw2));
        float lo, hi; upk(dd2, lo, hi);
        if (fminf(lo, hi) < d3) {
            INS(lo, 2*j);
            INS(hi, 2*j + 1);
        }
    }

    float t0 = sqrtf(fmaxf(d0, 1e-12f));
    float t1 = sqrtf(fmaxf(d1, 1e-12f));
    float t2 = sqrtf(fmaxf(d2, 1e-12f));
    float t3 = sqrtf(fmaxf(d3, 1e-12f));
    float w0 = 1.f/(t0 + 1e-8f), w1 = 1.f/(t1 + 1e-8f);
    float w2 = 1.f/(t2 + 1e-8f), w3 = 1.f/(t3 + 1e-8f);
    float scale = attw / (w0 + w1 + w2 + w3);

    const int q = b*QPB + qi;
    *(int4*)  (g_idx + 4*q) = make_int4(i0, i1, i2, i3);
    *(float4*)(g_w   + 4*q) = make_float4(w0*scale, w1*scale, w2*scale, w3*scale);
}

// ---------------- gather values + weighted sum over (p, k) -----------------
// one warp per (b,l); lane = d channel
__global__ void combine_k() {
    int gw = (blockIdx.x * blockDim.x + threadIdx.x) >> 5;
    int lane = threadIdx.x & 31;
    if (gw >= NH*LB) return;
    int b = gw >> 10;
    int l = gw & (LB - 1);
    int n_q = b >> 3, h_q = b & 7;       // output placement
    int n_v = b & 1,  h_v = b >> 1;      // value slice (reference transpose quirk)
    const float* vbase = g_val + n_v*(LB*EB) + h_v*DB + lane;
    int qb = (b*QPB + l*PB) * KK;
    const int4*   ip = (const int4*)  (g_idx + qb);
    const float4* wp = (const float4*)(g_w   + qb);
    float acc = 0.f;
    #pragma unroll
    for (int j4 = 0; j4 < 4; j4++) {
        int4   ii = ip[j4];
        float4 ww = wp[j4];
        acc = fmaf(ww.x, vbase[ii.x*EB], acc);
        acc = fmaf(ww.y, vbase[ii.y*EB], acc);
        acc = fmaf(ww.z, vbase[ii.z*EB], acc);
        acc = fmaf(ww.w, vbase[ii.w*EB], acc);
    }
    g_A[(n_q*LB + l)*EB + h_q*DB + lane] = acc;
}

// ---------------------------------------------------------------------------
extern "C" void kernel_launch(void* const* d_in, const int* in_sizes, int n_in,
                              void* d_out, int out_size) {
    const float* q      = (const float*)d_in[0];
    const float* rp     = (const float*)d_in[1];
    const float* W_off  = (const float*)d_in[2];
    const float* b_off  = (const float*)d_in[3];
    const float* W_attn = (const float*)d_in[4];
    const float* b_attn = (const float*)d_in[5];
    const float* W_val  = (const float*)d_in[6];
    const float* b_val  = (const float*)d_in[7];
    const float* W_out  = (const float*)d_in[8];
    const float* b_out  = (const float*)d_in[9];
    float* out = (float*)d_out;

    dim3 blk(256);
    gemm_val_k<<<dim3(4, 32), blk>>>(q, W_val, b_val);
    gemm_oa_k <<<dim3(2, 32), blk>>>(q, W_off, b_off, W_attn, b_attn);
    knn_k     <<<dim3(16, 16), blk>>>(rp);
    combine_k <<<2048, blk>>>();
    gemm_out_k<<<dim3(4, 32), blk>>>(W_out, b_out, out);
}